// round 3
// baseline (speedup 1.0000x reference)
#include <cuda_runtime.h>
#include <cuda_bf16.h>
#include <cstdint>
#include <cstdio>

// Problem dims
#define S_LEN 512
#define BATCH 64
#define EDIM  512
#define HDIM  1024
#define G4H   4096
#define NTAGS 13
#define DFF   256

// ---------------- device scratch (no allocations allowed) ----------------
__device__ __nv_bfloat16 g_Wih[(size_t)NTAGS * G4H * EDIM];   // 54.5 MB
__device__ __nv_bfloat16 g_Whh[(size_t)NTAGS * G4H * HDIM];   // 109 MB
__device__ float         g_bias[NTAGS * G4H];
__device__ __nv_bfloat16 g_x[(size_t)S_LEN * BATCH * EDIM];   // [S][B][E] bf16
__device__ float         g_xproj[(size_t)S_LEN * BATCH * G4H];// [S][B][4H] fp32, 536MB
__device__ __nv_bfloat16 g_hbuf[2][BATCH * HDIM];             // double-buffered h (bf16)
__device__ float         g_hfinal[BATCH * HDIM];
__device__ unsigned          g_bar_count;
__device__ volatile unsigned g_bar_gen;

// ---------------- ptx helpers ----------------
__device__ __forceinline__ void ldsm_x4(uint32_t& r0, uint32_t& r1, uint32_t& r2,
                                        uint32_t& r3, const void* smem_ptr) {
    uint32_t addr = (uint32_t)__cvta_generic_to_shared(smem_ptr);
    asm volatile("ldmatrix.sync.aligned.m8n8.x4.shared.b16 {%0,%1,%2,%3}, [%4];"
                 : "=r"(r0), "=r"(r1), "=r"(r2), "=r"(r3) : "r"(addr));
}

__device__ __forceinline__ void mma_bf16(float c[4], uint32_t a0, uint32_t a1,
                                         uint32_t a2, uint32_t a3,
                                         uint32_t b0, uint32_t b1) {
    asm volatile(
        "mma.sync.aligned.m16n8k16.row.col.f32.bf16.bf16.f32 "
        "{%0,%1,%2,%3}, {%4,%5,%6,%7}, {%8,%9}, {%0,%1,%2,%3};\n"
        : "+f"(c[0]), "+f"(c[1]), "+f"(c[2]), "+f"(c[3])
        : "r"(a0), "r"(a1), "r"(a2), "r"(a3), "r"(b0), "r"(b1));
}

__device__ __forceinline__ uint4 ldcg_u4(const void* p) {
    uint4 v;
    asm volatile("ld.global.cg.v4.u32 {%0,%1,%2,%3}, [%4];"
                 : "=r"(v.x), "=r"(v.y), "=r"(v.z), "=r"(v.w) : "l"(p));
    return v;
}

__device__ __forceinline__ float sigmoidf_(float x) { return 1.0f / (1.0f + expf(-x)); }

// ---------------- kernel 1: fp32 -> bf16 weight conversion ----------------
__global__ void cvt_weights_kernel(const float* __restrict__ wih,
                                   const float* __restrict__ whh) {
    const size_t n1 = (size_t)NTAGS * G4H * EDIM / 4;  // 6,815,744 float4s
    const size_t n2 = (size_t)NTAGS * G4H * HDIM / 4;  // 13,631,488 float4s
    size_t i = (size_t)blockIdx.x * blockDim.x + threadIdx.x;
    if (i < n1) {
        float4 v = ((const float4*)wih)[i];
        __nv_bfloat162 lo, hi;
        lo.x = __float2bfloat16(v.x); lo.y = __float2bfloat16(v.y);
        hi.x = __float2bfloat16(v.z); hi.y = __float2bfloat16(v.w);
        ((__nv_bfloat162*)g_Wih)[2 * i]     = lo;
        ((__nv_bfloat162*)g_Wih)[2 * i + 1] = hi;
    }
    if (i < n2) {
        float4 v = ((const float4*)whh)[i];
        __nv_bfloat162 lo, hi;
        lo.x = __float2bfloat16(v.x); lo.y = __float2bfloat16(v.y);
        hi.x = __float2bfloat16(v.z); hi.y = __float2bfloat16(v.w);
        ((__nv_bfloat162*)g_Whh)[2 * i]     = lo;
        ((__nv_bfloat162*)g_Whh)[2 * i + 1] = hi;
    }
}

// ---------------- kernel 2: bias combine + zero h0 ----------------
__global__ void bias_zero_kernel(const float* __restrict__ b_ih,
                                 const float* __restrict__ b_hh) {
    int i = blockIdx.x * blockDim.x + threadIdx.x;
    if (i < NTAGS * G4H) g_bias[i] = b_ih[i] + b_hh[i];
    if (i < BATCH * HDIM) g_hbuf[0][i] = __float2bfloat16(0.0f);
}

// ---------------- kernel 3: embedding gather [B,S] -> x[S][B][E] bf16 ------
__global__ void embed_kernel(const int* __restrict__ tokens,
                             const float* __restrict__ emb) {
    const int s = blockIdx.x, b = blockIdx.y, t = threadIdx.x;  // 128 threads
    const int tok = __ldg(tokens + b * S_LEN + s);
    float4 v = ((const float4*)(emb + (size_t)tok * EDIM))[t];
    __nv_bfloat162 lo, hi;
    lo.x = __float2bfloat16(v.x); lo.y = __float2bfloat16(v.y);
    hi.x = __float2bfloat16(v.z); hi.y = __float2bfloat16(v.w);
    __nv_bfloat162* dst = (__nv_bfloat162*)(g_x + ((size_t)s * BATCH + b) * EDIM);
    dst[2 * t] = lo; dst[2 * t + 1] = hi;
}

// ---------------- kernel 4: input projection -------------------------------
// xproj[s][b][r] = sum_k x[s][b][k] * Wih[tag_s][r][k] + bias[tag_s][r]
// grid: (16 n-tiles of 256 rows, 512 steps), 256 thr, smem = x tile 64x520 bf16
#define XS_LD 520
__global__ void __launch_bounds__(256)
input_proj_kernel(const int* __restrict__ tags) {
    extern __shared__ __nv_bfloat16 x_sm[];  // [64][XS_LD]
    const int s = blockIdx.y;
    const int n0 = blockIdx.x * 256;
    const int tid = threadIdx.x, warp = tid >> 5, lane = tid & 31;
    const int gid = lane >> 2, tig = lane & 3;
    const int tag = __ldg(tags + s);

    // stage x[s] : 64 rows x 512 bf16 (64 uint4 per row)
    const __nv_bfloat16* xg = g_x + (size_t)s * BATCH * EDIM;
    for (int i = tid; i < 64 * 64; i += 256) {
        int r = i >> 6, seg = i & 63;
        *(uint4*)(x_sm + r * XS_LD + seg * 8) = *(const uint4*)(xg + r * EDIM + seg * 8);
    }
    __syncthreads();

    float acc[4][4][4];  // [mtile][ntile][frag]
    const float* bias = g_bias + tag * G4H;
#pragma unroll
    for (int t = 0; t < 4; t++) {
        int col = n0 + warp * 32 + t * 8 + tig * 2;
        float bv0 = __ldg(bias + col), bv1 = __ldg(bias + col + 1);
#pragma unroll
        for (int mt = 0; mt < 4; mt++) {
            acc[mt][t][0] = bv0; acc[mt][t][1] = bv1;
            acc[mt][t][2] = bv0; acc[mt][t][3] = bv1;
        }
    }
    const __nv_bfloat16* Wb = g_Wih + (size_t)tag * G4H * EDIM;
    const __nv_bfloat16* wp[4];
#pragma unroll
    for (int t = 0; t < 4; t++)
        wp[t] = Wb + (size_t)(n0 + warp * 32 + t * 8 + gid) * EDIM + tig * 2;

    const int lrow = lane & 15, lkoff = (lane >> 4) * 8;
#pragma unroll 2
    for (int k = 0; k < EDIM; k += 16) {
        uint32_t a[4][4];
#pragma unroll
        for (int mt = 0; mt < 4; mt++)
            ldsm_x4(a[mt][0], a[mt][1], a[mt][2], a[mt][3],
                    x_sm + (mt * 16 + lrow) * XS_LD + k + lkoff);
#pragma unroll
        for (int t = 0; t < 4; t++) {
            uint32_t b0 = *(const uint32_t*)(wp[t] + k);
            uint32_t b1 = *(const uint32_t*)(wp[t] + k + 8);
#pragma unroll
            for (int mt = 0; mt < 4; mt++)
                mma_bf16(acc[mt][t], a[mt][0], a[mt][1], a[mt][2], a[mt][3], b0, b1);
        }
    }
    float* xp = g_xproj + (size_t)s * BATCH * G4H;
#pragma unroll
    for (int mt = 0; mt < 4; mt++) {
        int b = mt * 16 + gid;
#pragma unroll
        for (int t = 0; t < 4; t++) {
            int col = n0 + warp * 32 + t * 8 + tig * 2;
            *(float2*)(xp + (size_t)b * G4H + col)       = make_float2(acc[mt][t][0], acc[mt][t][1]);
            *(float2*)(xp + (size_t)(b + 8) * G4H + col) = make_float2(acc[mt][t][2], acc[mt][t][3]);
        }
    }
}

// ---------------- kernel 5: persistent recurrent LSTM ----------------------
// 128 CTAs x 256 thr. CTA c owns h columns [8c, 8c+8) => 32 gate rows.
// Per step: stage full h (bf16, .cg) in smem, GEMM M=64 N=32 K=1024 via mma,
// elementwise LSTM update on owned slice, grid barrier.
#define RK_NCTA 128
#define H_LD 1032  // padded smem row (bf16 elems), 16B-aligned stride, conflict-free
#define SM_H_BYTES (64 * H_LD * 2)
#define SM_G_BYTES (4 * 64 * 8 * 4)
#define SM_C_BYTES (64 * 8 * 4)
#define RK_SMEM (SM_H_BYTES + SM_G_BYTES + SM_C_BYTES)

__device__ __forceinline__ void grid_barrier() {
    __syncthreads();
    if (threadIdx.x == 0) {
        unsigned my = g_bar_gen;
        __threadfence();
        unsigned t = atomicAdd(&g_bar_count, 1);
        if (t == gridDim.x - 1) {
            g_bar_count = 0;
            __threadfence();
            g_bar_gen = my + 1;
        } else {
            while (g_bar_gen == my) { }
        }
        __threadfence();
    }
    __syncthreads();
}

__global__ void __launch_bounds__(256, 1)
lstm_recurrent_kernel(const int* __restrict__ tags) {
    extern __shared__ char smem_raw[];
    __nv_bfloat16* h_sm  = (__nv_bfloat16*)smem_raw;                 // [64][H_LD]
    float* gates_sm = (float*)(smem_raw + SM_H_BYTES);               // [4][64][8]
    float* c_sm     = (float*)(smem_raw + SM_H_BYTES + SM_G_BYTES);  // [64][8]

    const int tid = threadIdx.x, warp = tid >> 5, lane = tid & 31;
    const int gid = lane >> 2, tig = lane & 3;
    const int hc0 = blockIdx.x * 8;
    const int g = warp & 3;        // gate index (i,f,g,o)
    const int mhalf = warp >> 2;   // 0/1 -> batch rows 0-31 / 32-63
    const int lrow = lane & 15, lkoff = (lane >> 4) * 8;

    for (int i = tid; i < 64 * 8; i += 256) c_sm[i] = 0.0f;

    // per-lane weight row base (within a tag): row = g*1024 + hc0 + gid
    const size_t wrow_off = (size_t)(g * HDIM + hc0 + gid) * HDIM + tig * 2;

    for (int s = 0; s < S_LEN; s++) {
        // stage h_{s-1} (bypass L1: incoherent across the grid barrier)
        const __nv_bfloat16* hin = g_hbuf[s & 1];
        for (int i = tid; i < 64 * 128; i += 256) {  // 128 x 16B per row
            int r = i >> 7, seg = i & 127;
            uint4 v = ldcg_u4(hin + r * HDIM + seg * 8);
            *(uint4*)(h_sm + r * H_LD + seg * 8) = v;
        }
        const int tag = __ldg(tags + s);
        const __nv_bfloat16* W = g_Whh + (size_t)tag * G4H * HDIM + wrow_off;

        // init accumulators from xproj (contains x-proj + biases)
        const float* xp = g_xproj + (size_t)s * BATCH * G4H;
        float acc[2][4];
#pragma unroll
        for (int t = 0; t < 2; t++) {
            int br = mhalf * 32 + t * 16 + gid;
            int col = g * HDIM + hc0 + tig * 2;
            float2 v0 = *(const float2*)(xp + (size_t)br * G4H + col);
            float2 v1 = *(const float2*)(xp + (size_t)(br + 8) * G4H + col);
            acc[t][0] = v0.x; acc[t][1] = v0.y; acc[t][2] = v1.x; acc[t][3] = v1.y;
        }
        __syncthreads();  // h_sm ready (also: prior gates_sm reads completed)

#pragma unroll 4
        for (int k = 0; k < HDIM; k += 16) {
            uint32_t b0 = *(const uint32_t*)(W + k);
            uint32_t b1 = *(const uint32_t*)(W + k + 8);
#pragma unroll
            for (int t = 0; t < 2; t++) {
                uint32_t a0, a1, a2, a3;
                ldsm_x4(a0, a1, a2, a3,
                        h_sm + (mhalf * 32 + t * 16 + lrow) * H_LD + k + lkoff);
                mma_bf16(acc[t], a0, a1, a2, a3, b0, b1);
            }
        }
        // stash gate pre-activations
#pragma unroll
        for (int t = 0; t < 2; t++) {
            int br = mhalf * 32 + t * 16 + gid;
            float* gp  = gates_sm + (g * 64 + br) * 8 + tig * 2;
            float* gp2 = gates_sm + (g * 64 + br + 8) * 8 + tig * 2;
            gp[0] = acc[t][0];  gp[1] = acc[t][1];
            gp2[0] = acc[t][2]; gp2[1] = acc[t][3];
        }
        __syncthreads();

        // elementwise LSTM update on owned slice (512 elems)
        __nv_bfloat16* hout = g_hbuf[(s + 1) & 1];
        for (int e = tid; e < 512; e += 256) {
            int b = e >> 3, j = e & 7;
            float gi = gates_sm[(0 * 64 + b) * 8 + j];
            float gf = gates_sm[(1 * 64 + b) * 8 + j];
            float gg = gates_sm[(2 * 64 + b) * 8 + j];
            float go = gates_sm[(3 * 64 + b) * 8 + j];
            float cn = sigmoidf_(gf) * c_sm[b * 8 + j] + sigmoidf_(gi) * tanhf(gg);
            float hn = sigmoidf_(go) * tanhf(cn);
            c_sm[b * 8 + j] = cn;
            hout[b * HDIM + hc0 + j] = __float2bfloat16(hn);
            if (s == S_LEN - 1) g_hfinal[b * HDIM + hc0 + j] = hn;
        }
        grid_barrier();
    }
}

// ---------------- kernel 6: final MLP + sigmoid ----------------------------
__global__ void mlp_kernel(const float* __restrict__ W1, const float* __restrict__ b1,
                           const float* __restrict__ W2, const float* __restrict__ b2,
                           float* __restrict__ out) {
    __shared__ float h_sm[HDIM];
    __shared__ float hid[DFF];
    __shared__ float red[8];
    const int b = blockIdx.x, tid = threadIdx.x, warp = tid >> 5, lane = tid & 31;
    for (int i = tid; i < HDIM; i += 256) h_sm[i] = g_hfinal[b * HDIM + i];
    __syncthreads();
    for (int j = warp; j < DFF; j += 8) {
        const float* w = W1 + (size_t)j * HDIM;
        float sum = 0.0f;
        for (int k = lane; k < HDIM; k += 32) sum += h_sm[k] * __ldg(w + k);
#pragma unroll
        for (int o = 16; o; o >>= 1) sum += __shfl_xor_sync(0xffffffffu, sum, o);
        if (lane == 0) hid[j] = fmaxf(sum + __ldg(b1 + j), 0.0f);
    }
    __syncthreads();
    float p = hid[tid] * __ldg(W2 + tid);
#pragma unroll
    for (int o = 16; o; o >>= 1) p += __shfl_xor_sync(0xffffffffu, p, o);
    if (lane == 0) red[warp] = p;
    __syncthreads();
    if (tid == 0) {
        float sv = __ldg(b2);
        for (int i = 0; i < 8; i++) sv += red[i];
        out[b] = 1.0f / (1.0f + expf(-sv));
    }
}

// ---------------- launch ----------------
extern "C" void kernel_launch(void* const* d_in, const int* in_sizes, int n_in,
                              void* d_out, int out_size) {
    const int*   tokens = (const int*)d_in[0];
    const int*   tags   = (const int*)d_in[1];
    const float* emb_w  = (const float*)d_in[2];
    const float* W_ih   = (const float*)d_in[3];
    const float* W_hh   = (const float*)d_in[4];
    const float* b_ih   = (const float*)d_in[5];
    const float* b_hh   = (const float*)d_in[6];
    const float* W1     = (const float*)d_in[7];
    const float* b1     = (const float*)d_in[8];
    const float* W2     = (const float*)d_in[9];
    const float* b2     = (const float*)d_in[10];
    float* out = (float*)d_out;

    cudaFuncSetAttribute(input_proj_kernel,
                         cudaFuncAttributeMaxDynamicSharedMemorySize, 64 * XS_LD * 2);
    cudaFuncSetAttribute(lstm_recurrent_kernel,
                         cudaFuncAttributeMaxDynamicSharedMemorySize, RK_SMEM);

    // 1) weights -> bf16
    {
        size_t n4 = (size_t)NTAGS * G4H * HDIM / 4;  // larger of the two
        int blocks = (int)((n4 + 255) / 256);
        cvt_weights_kernel<<<blocks, 256>>>(W_ih, W_hh);
    }
    // 2) bias combine + zero h0
    bias_zero_kernel<<<(BATCH * HDIM + 255) / 256, 256>>>(b_ih, b_hh);
    // 3) embedding gather (transpose to [S][B][E] bf16)
    embed_kernel<<<dim3(S_LEN, BATCH), 128>>>(tokens, emb_w);
    // 4) batched input projection
    input_proj_kernel<<<dim3(G4H / 256, S_LEN), 256, 64 * XS_LD * 2>>>(tags);
    // 5) persistent recurrent LSTM (512 steps, grid barrier)
    lstm_recurrent_kernel<<<RK_NCTA, 256, RK_SMEM>>>(tags);
    // 6) head MLP + sigmoid
    mlp_kernel<<<BATCH, 256>>>(W1, b1, W2, b2, out);
}

// round 6
// speedup vs baseline: 1.4035x; 1.4035x over previous
#include <cuda_runtime.h>
#include <cuda_bf16.h>
#include <cstdint>
#include <cstdio>

// Problem dims
#define S_LEN 512
#define BATCH 64
#define EDIM  512
#define HDIM  1024
#define G4H   4096
#define NTAGS 13
#define DFF   256

// ---------------- device scratch (no allocations allowed) ----------------
// W matrices stored in a PERMUTED bf16 layout: within each 16-element k-group,
// positions [4t..4t+3] hold source elements (2t, 2t+1, 2t+8, 2t+9), t=0..3.
// A lane with quad-id t then reads its mma B-fragment pair (b0,b1) as ONE
// 8-byte load at group_base + 4t.
__device__ __nv_bfloat16 g_Wih[(size_t)NTAGS * G4H * EDIM];   // 54.5 MB (permuted)
__device__ __nv_bfloat16 g_Whh[(size_t)NTAGS * G4H * HDIM];   // 109 MB (permuted)
__device__ float         g_bias[NTAGS * G4H];
__device__ __nv_bfloat16 g_x[(size_t)S_LEN * BATCH * EDIM];   // [S][B][E] bf16
__device__ float         g_xproj[(size_t)S_LEN * BATCH * G4H];// [S][B][4H] fp32
__device__ __nv_bfloat16 g_hbuf[2][BATCH * HDIM];             // double-buffered h
__device__ float         g_hfinal[BATCH * HDIM];
__device__ unsigned          g_bar_count;
__device__ volatile unsigned g_bar_gen;

// ---------------- ptx helpers ----------------
__device__ __forceinline__ void ldsm_x4(uint32_t& r0, uint32_t& r1, uint32_t& r2,
                                        uint32_t& r3, const void* smem_ptr) {
    uint32_t addr = (uint32_t)__cvta_generic_to_shared(smem_ptr);
    asm volatile("ldmatrix.sync.aligned.m8n8.x4.shared.b16 {%0,%1,%2,%3}, [%4];"
                 : "=r"(r0), "=r"(r1), "=r"(r2), "=r"(r3) : "r"(addr));
}

__device__ __forceinline__ void mma_bf16(float c[4], uint32_t a0, uint32_t a1,
                                         uint32_t a2, uint32_t a3,
                                         uint32_t b0, uint32_t b1) {
    asm volatile(
        "mma.sync.aligned.m16n8k16.row.col.f32.bf16.bf16.f32 "
        "{%0,%1,%2,%3}, {%4,%5,%6,%7}, {%8,%9}, {%0,%1,%2,%3};\n"
        : "+f"(c[0]), "+f"(c[1]), "+f"(c[2]), "+f"(c[3])
        : "r"(a0), "r"(a1), "r"(a2), "r"(a3), "r"(b0), "r"(b1));
}

__device__ __forceinline__ void cp_async16(void* smem_dst, const void* gsrc) {
    uint32_t d = (uint32_t)__cvta_generic_to_shared(smem_dst);
    asm volatile("cp.async.cg.shared.global [%0], [%1], 16;" :: "r"(d), "l"(gsrc));
}

__device__ __forceinline__ float sigmoidf_(float x) { return 1.0f / (1.0f + expf(-x)); }

// ---------------- kernel 1: fp32 -> bf16 weight conversion (permuted) ------
__global__ void cvt_weights_kernel(const float* __restrict__ wih,
                                   const float* __restrict__ whh) {
    const size_t n1 = (size_t)NTAGS * G4H * EDIM / 4;
    const size_t n2 = (size_t)NTAGS * G4H * HDIM / 4;
    size_t i = (size_t)blockIdx.x * blockDim.x + threadIdx.x;
    // float4 at src offset q (q%4==0), qi = q%16:
    //   pair (qi,qi+1) -> d0 ; pair (qi+2,qi+3) -> d0+4
    //   d0 = ((qi&4)<<1) | ((qi>>3)<<1)
    if (i < n1) {
        float4 v = ((const float4*)wih)[i];
        size_t q = 4 * i;
        unsigned qi = (unsigned)(q & 15);
        size_t base = q - qi;
        unsigned d0 = ((qi & 4u) << 1) | ((qi >> 3) << 1);
        __nv_bfloat162 p0, p1;
        p0.x = __float2bfloat16(v.x); p0.y = __float2bfloat16(v.y);
        p1.x = __float2bfloat16(v.z); p1.y = __float2bfloat16(v.w);
        *(__nv_bfloat162*)(g_Wih + base + d0)     = p0;
        *(__nv_bfloat162*)(g_Wih + base + d0 + 4) = p1;
    }
    if (i < n2) {
        float4 v = ((const float4*)whh)[i];
        size_t q = 4 * i;
        unsigned qi = (unsigned)(q & 15);
        size_t base = q - qi;
        unsigned d0 = ((qi & 4u) << 1) | ((qi >> 3) << 1);
        __nv_bfloat162 p0, p1;
        p0.x = __float2bfloat16(v.x); p0.y = __float2bfloat16(v.y);
        p1.x = __float2bfloat16(v.z); p1.y = __float2bfloat16(v.w);
        *(__nv_bfloat162*)(g_Whh + base + d0)     = p0;
        *(__nv_bfloat162*)(g_Whh + base + d0 + 4) = p1;
    }
}

// ---------------- kernel 2: bias combine + zero h0 + barrier reset ---------
__global__ void bias_zero_kernel(const float* __restrict__ b_ih,
                                 const float* __restrict__ b_hh) {
    int i = blockIdx.x * blockDim.x + threadIdx.x;
    if (i == 0) { g_bar_count = 0; g_bar_gen = 0; }
    if (i < NTAGS * G4H) g_bias[i] = b_ih[i] + b_hh[i];
    if (i < BATCH * HDIM) g_hbuf[0][i] = __float2bfloat16(0.0f);
}

// ---------------- kernel 3: embedding gather [B,S] -> x[S][B][E] bf16 ------
__global__ void embed_kernel(const int* __restrict__ tokens,
                             const float* __restrict__ emb) {
    const int s = blockIdx.x, b = blockIdx.y, t = threadIdx.x;  // 128 threads
    const int tok = __ldg(tokens + b * S_LEN + s);
    float4 v = ((const float4*)(emb + (size_t)tok * EDIM))[t];
    __nv_bfloat162 lo, hi;
    lo.x = __float2bfloat16(v.x); lo.y = __float2bfloat16(v.y);
    hi.x = __float2bfloat16(v.z); hi.y = __float2bfloat16(v.w);
    __nv_bfloat162* dst = (__nv_bfloat162*)(g_x + ((size_t)s * BATCH + b) * EDIM);
    dst[2 * t] = lo; dst[2 * t + 1] = hi;
}

// ---------------- kernel 4: input projection -------------------------------
#define XS_LD 520
__global__ void __launch_bounds__(256, 2)
input_proj_kernel(const int* __restrict__ tags) {
    extern __shared__ __nv_bfloat16 x_sm[];  // [64][XS_LD]
    const int s = blockIdx.y;
    const int n0 = blockIdx.x * 256;
    const int tid = threadIdx.x, warp = tid >> 5, lane = tid & 31;
    const int gid = lane >> 2, tig = lane & 3;
    const int tag = __ldg(tags + s);

    const __nv_bfloat16* xg = g_x + (size_t)s * BATCH * EDIM;
    for (int i = tid; i < 64 * 64; i += 256) {
        int r = i >> 6, seg = i & 63;
        *(uint4*)(x_sm + r * XS_LD + seg * 8) = *(const uint4*)(xg + r * EDIM + seg * 8);
    }
    __syncthreads();

    float acc[4][4][4];
    const float* bias = g_bias + tag * G4H;
#pragma unroll
    for (int t = 0; t < 4; t++) {
        int col = n0 + warp * 32 + t * 8 + tig * 2;
        float bv0 = __ldg(bias + col), bv1 = __ldg(bias + col + 1);
#pragma unroll
        for (int mt = 0; mt < 4; mt++) {
            acc[mt][t][0] = bv0; acc[mt][t][1] = bv1;
            acc[mt][t][2] = bv0; acc[mt][t][3] = bv1;
        }
    }
    const __nv_bfloat16* Wb = g_Wih + (size_t)tag * G4H * EDIM;
    const __nv_bfloat16* wp[4];
#pragma unroll
    for (int t = 0; t < 4; t++)   // permuted layout: lane offset tig*4 in group
        wp[t] = Wb + (size_t)(n0 + warp * 32 + t * 8 + gid) * EDIM + tig * 4;

    const int lrow = lane & 15, lkoff = (lane >> 4) * 8;
#pragma unroll 2
    for (int k = 0; k < EDIM; k += 16) {
        uint32_t a[4][4];
#pragma unroll
        for (int mt = 0; mt < 4; mt++)
            ldsm_x4(a[mt][0], a[mt][1], a[mt][2], a[mt][3],
                    x_sm + (mt * 16 + lrow) * XS_LD + k + lkoff);
#pragma unroll
        for (int t = 0; t < 4; t++) {
            uint2 bv = *(const uint2*)(wp[t] + k);   // LDG.64: (b0,b1)
#pragma unroll
            for (int mt = 0; mt < 4; mt++)
                mma_bf16(acc[mt][t], a[mt][0], a[mt][1], a[mt][2], a[mt][3], bv.x, bv.y);
        }
    }
    float* xp = g_xproj + (size_t)s * BATCH * G4H;
#pragma unroll
    for (int mt = 0; mt < 4; mt++) {
        int b = mt * 16 + gid;
#pragma unroll
        for (int t = 0; t < 4; t++) {
            int col = n0 + warp * 32 + t * 8 + tig * 2;
            *(float2*)(xp + (size_t)b * G4H + col)       = make_float2(acc[mt][t][0], acc[mt][t][1]);
            *(float2*)(xp + (size_t)(b + 8) * G4H + col) = make_float2(acc[mt][t][2], acc[mt][t][3]);
        }
    }
}

// ---------------- kernel 5: persistent recurrent LSTM ----------------------
#define RK_NCTA 128
#define H_LD 1032
#define SM_H_BYTES (64 * H_LD * 2)
#define SM_G_BYTES (4 * 64 * 8 * 4)
#define SM_C_BYTES (64 * 8 * 4)
#define RK_SMEM (SM_H_BYTES + SM_G_BYTES + SM_C_BYTES)

__global__ void __launch_bounds__(256, 1)
lstm_recurrent_kernel(const int* __restrict__ tags) {
    extern __shared__ char smem_raw[];
    __nv_bfloat16* h_sm = (__nv_bfloat16*)smem_raw;                  // [64][H_LD]
    float* gates_sm = (float*)(smem_raw + SM_H_BYTES);               // [4][64][8]
    float* c_sm     = (float*)(smem_raw + SM_H_BYTES + SM_G_BYTES);  // [64][8]

    const int tid = threadIdx.x, warp = tid >> 5, lane = tid & 31;
    const int gid = lane >> 2, tig = lane & 3;
    const int hc0 = blockIdx.x * 8;
    const int g = warp & 3;
    const int mhalf = warp >> 2;
    const int lrow = lane & 15, lkoff = (lane >> 4) * 8;
    const unsigned bidr = blockIdx.x;

    for (int i = tid; i < 64 * 8; i += 256) c_sm[i] = 0.0f;

    // permuted layout: lane offset tig*4 within each 16-k group
    const size_t wrow_off = (size_t)(g * HDIM + hc0 + gid) * HDIM + tig * 4;

    float acc[2][4];
    // prologue: acc init for step 0 (xproj already includes x-proj + biases)
    {
        const float* xp = g_xproj;
#pragma unroll
        for (int t = 0; t < 2; t++) {
            int br = mhalf * 32 + t * 16 + gid;
            int col = g * HDIM + hc0 + tig * 2;
            float2 v0 = *(const float2*)(xp + (size_t)br * G4H + col);
            float2 v1 = *(const float2*)(xp + (size_t)(br + 8) * G4H + col);
            acc[t][0] = v0.x; acc[t][1] = v0.y; acc[t][2] = v1.x; acc[t][3] = v1.y;
        }
    }

    for (int s = 0; s < S_LEN; s++) {
        const __nv_bfloat16* W =
            g_Whh + (size_t)__ldg(tags + s) * G4H * HDIM + wrow_off;
        const __nv_bfloat16* hin = g_hbuf[s & 1];

        // --- stage h via cp.async.cg in 2 k-chunks (rotated by CTA id) ---
#pragma unroll
        for (int c = 0; c < 2; c++) {
#pragma unroll 4
            for (int j = 0; j < 16; j++) {
                int i = tid + j * 256;            // 0..4095
                int r = i >> 6;
                int seg = (int)(((unsigned)(i & 63) + bidr) & 63u) + c * 64;
                cp_async16(h_sm + r * H_LD + seg * 8, hin + r * HDIM + seg * 8);
            }
            asm volatile("cp.async.commit_group;");
        }
        asm volatile("cp.async.wait_group 1;");
        __syncthreads();   // chunk0 (k 0..511) staged CTA-wide

        // --- mma chunk0, overlapped with chunk1 transfer ---
#pragma unroll 8
        for (int k = 0; k < 512; k += 16) {
            uint2 bv = *(const uint2*)(W + k);
#pragma unroll
            for (int t = 0; t < 2; t++) {
                uint32_t a0, a1, a2, a3;
                ldsm_x4(a0, a1, a2, a3,
                        h_sm + (mhalf * 32 + t * 16 + lrow) * H_LD + k + lkoff);
                mma_bf16(acc[t], a0, a1, a2, a3, bv.x, bv.y);
            }
        }
        asm volatile("cp.async.wait_group 0;");
        __syncthreads();   // chunk1 staged
#pragma unroll 8
        for (int k = 512; k < 1024; k += 16) {
            uint2 bv = *(const uint2*)(W + k);
#pragma unroll
            for (int t = 0; t < 2; t++) {
                uint32_t a0, a1, a2, a3;
                ldsm_x4(a0, a1, a2, a3,
                        h_sm + (mhalf * 32 + t * 16 + lrow) * H_LD + k + lkoff);
                mma_bf16(acc[t], a0, a1, a2, a3, bv.x, bv.y);
            }
        }

        // --- stash gate pre-activations ---
#pragma unroll
        for (int t = 0; t < 2; t++) {
            int br = mhalf * 32 + t * 16 + gid;
            float* gp  = gates_sm + (g * 64 + br) * 8 + tig * 2;
            float* gp2 = gates_sm + (g * 64 + br + 8) * 8 + tig * 2;
            gp[0] = acc[t][0];  gp[1] = acc[t][1];
            gp2[0] = acc[t][2]; gp2[1] = acc[t][3];
        }
        __syncthreads();

        // --- elementwise LSTM update on owned slice ---
        __nv_bfloat16* hout = g_hbuf[(s + 1) & 1];
        for (int e = tid; e < 512; e += 256) {
            int b = e >> 3, j = e & 7;
            float gi = gates_sm[(0 * 64 + b) * 8 + j];
            float gf = gates_sm[(1 * 64 + b) * 8 + j];
            float gg = gates_sm[(2 * 64 + b) * 8 + j];
            float go = gates_sm[(3 * 64 + b) * 8 + j];
            float cn = sigmoidf_(gf) * c_sm[b * 8 + j] + sigmoidf_(gi) * tanhf(gg);
            float hn = sigmoidf_(go) * tanhf(cn);
            c_sm[b * 8 + j] = cn;
            hout[b * HDIM + hc0 + j] = __float2bfloat16(hn);
            if (s == S_LEN - 1) g_hfinal[b * HDIM + hc0 + j] = hn;
        }
        __syncthreads();   // all h stores of this CTA issued

        // --- R2-proven generation barrier, split into arrive / overlap / wait
        unsigned my_gen = 0;
        bool is_releaser = false;
        if (tid == 0) {
            my_gen = g_bar_gen;
            __threadfence();                       // publish h stores gpu-wide
            unsigned t = atomicAdd(&g_bar_count, 1);
            if (t == gridDim.x - 1) {
                g_bar_count = 0;
                __threadfence();
                g_bar_gen = my_gen + 1;            // release everyone
                is_releaser = true;
            }
        }

        // --- overlapped with barrier wait: next-step acc init + W prefetch ---
        if (s + 1 < S_LEN) {
            const float* xp = g_xproj + (size_t)(s + 1) * BATCH * G4H;
#pragma unroll
            for (int t = 0; t < 2; t++) {
                int br = mhalf * 32 + t * 16 + gid;
                int col = g * HDIM + hc0 + tig * 2;
                float2 v0 = *(const float2*)(xp + (size_t)br * G4H + col);
                float2 v1 = *(const float2*)(xp + (size_t)(br + 8) * G4H + col);
                acc[t][0] = v0.x; acc[t][1] = v0.y; acc[t][2] = v1.x; acc[t][3] = v1.y;
            }
            int tag1 = __ldg(tags + s + 1);
            const char* wb = (const char*)g_Whh + (size_t)tag1 * G4H * HDIM * 2;
            for (int l = tid; l < 512; l += 256) {   // 512 x 128B lines = 64KB
                int g2 = l >> 7, off = (l & 127) << 7;
                const char* p = wb + (size_t)(g2 * HDIM + hc0) * HDIM * 2 + off;
                asm volatile("prefetch.global.L1 [%0];" :: "l"(p));
            }
        }

        // --- wait phase ---
        if (tid == 0) {
            if (!is_releaser) {
                while (g_bar_gen == my_gen) { __nanosleep(32); }
            }
            __threadfence();
        }
        __syncthreads();
    }
}

// ---------------- kernel 6: final MLP + sigmoid ----------------------------
__global__ void mlp_kernel(const float* __restrict__ W1, const float* __restrict__ b1,
                           const float* __restrict__ W2, const float* __restrict__ b2,
                           float* __restrict__ out) {
    __shared__ float h_sm[HDIM];
    __shared__ float hid[DFF];
    __shared__ float red[8];
    const int b = blockIdx.x, tid = threadIdx.x, warp = tid >> 5, lane = tid & 31;
    for (int i = tid; i < HDIM; i += 256) h_sm[i] = g_hfinal[b * HDIM + i];
    __syncthreads();
    for (int j = warp; j < DFF; j += 8) {
        const float* w = W1 + (size_t)j * HDIM;
        float sum = 0.0f;
        for (int k = lane; k < HDIM; k += 32) sum += h_sm[k] * __ldg(w + k);
#pragma unroll
        for (int o = 16; o; o >>= 1) sum += __shfl_xor_sync(0xffffffffu, sum, o);
        if (lane == 0) hid[j] = fmaxf(sum + __ldg(b1 + j), 0.0f);
    }
    __syncthreads();
    float p = hid[tid] * __ldg(W2 + tid);
#pragma unroll
    for (int o = 16; o; o >>= 1) p += __shfl_xor_sync(0xffffffffu, p, o);
    if (lane == 0) red[warp] = p;
    __syncthreads();
    if (tid == 0) {
        float sv = __ldg(b2);
        for (int i = 0; i < 8; i++) sv += red[i];
        out[b] = 1.0f / (1.0f + expf(-sv));
    }
}

// ---------------- launch ----------------
extern "C" void kernel_launch(void* const* d_in, const int* in_sizes, int n_in,
                              void* d_out, int out_size) {
    const int*   tokens = (const int*)d_in[0];
    const int*   tags   = (const int*)d_in[1];
    const float* emb_w  = (const float*)d_in[2];
    const float* W_ih   = (const float*)d_in[3];
    const float* W_hh   = (const float*)d_in[4];
    const float* b_ih   = (const float*)d_in[5];
    const float* b_hh   = (const float*)d_in[6];
    const float* W1     = (const float*)d_in[7];
    const float* b1     = (const float*)d_in[8];
    const float* W2     = (const float*)d_in[9];
    const float* b2     = (const float*)d_in[10];
    float* out = (float*)d_out;

    cudaFuncSetAttribute(input_proj_kernel,
                         cudaFuncAttributeMaxDynamicSharedMemorySize, 64 * XS_LD * 2);
    cudaFuncSetAttribute(lstm_recurrent_kernel,
                         cudaFuncAttributeMaxDynamicSharedMemorySize, RK_SMEM);

    {
        size_t n4 = (size_t)NTAGS * G4H * HDIM / 4;
        int blocks = (int)((n4 + 255) / 256);
        cvt_weights_kernel<<<blocks, 256>>>(W_ih, W_hh);
    }
    bias_zero_kernel<<<(BATCH * HDIM + 255) / 256, 256>>>(b_ih, b_hh);
    embed_kernel<<<dim3(S_LEN, BATCH), 128>>>(tokens, emb_w);
    input_proj_kernel<<<dim3(G4H / 256, S_LEN), 256, 64 * XS_LD * 2>>>(tags);
    lstm_recurrent_kernel<<<RK_NCTA, 256, RK_SMEM>>>(tags);
    mlp_kernel<<<BATCH, 256>>>(W1, b1, W2, b2, out);
}